// round 7
// baseline (speedup 1.0000x reference)
#include <cuda_runtime.h>
#include <cstdint>

// out[e] = dot(h[src[e]], h[dst[e]]), D=128 fp32, E=640000, N=10000.
//
// Strategy: bucket edges by src (counting sort) so each src vector is loaded
// ONCE per bucket into registers instead of once per edge. This halves the
// dominant gather traffic (655MB -> ~330MB through L1/L2).
// Passes: zero -> histogram -> scan -> scatter -> bucketed dot kernel.
// Scratch lives in __device__ globals (no allocation).

#define CAP_N 16384
#define CAP_E (1 << 20)

__device__ int g_counts[CAP_N];
__device__ int g_off[CAP_N];
__device__ int g_cursor[CAP_N];
__device__ int g_dst_sorted[CAP_E];
__device__ int g_eid_sorted[CAP_E];

__device__ __forceinline__ float dot4(float4 a, float4 b) {
    float s = a.x * b.x;
    s = fmaf(a.y, b.y, s);
    s = fmaf(a.z, b.z, s);
    s = fmaf(a.w, b.w, s);
    return s;
}

__device__ __forceinline__ float red2(float v) {   // xor16 + xor8
    v += __shfl_xor_sync(0xFFFFFFFFu, v, 16);
    v += __shfl_xor_sync(0xFFFFFFFFu, v, 8);
    return v;
}

__device__ __forceinline__ float red3(float v) {   // xor4 + xor2 + xor1
    v += __shfl_xor_sync(0xFFFFFFFFu, v, 4);
    v += __shfl_xor_sync(0xFFFFFFFFu, v, 2);
    v += __shfl_xor_sync(0xFFFFFFFFu, v, 1);
    return v;
}

__device__ __forceinline__ float warp_bfly_sum(float v) {
    #pragma unroll
    for (int off = 16; off > 0; off >>= 1)
        v += __shfl_xor_sync(0xFFFFFFFFu, v, off);
    return v;
}

// ── Pass 1: zero counts ─────────────────────────────────────────────────
__global__ void zero_kernel(int n_nodes) {
    int i = blockIdx.x * blockDim.x + threadIdx.x;
    if (i < n_nodes) g_counts[i] = 0;
}

// ── Pass 2: histogram of src ────────────────────────────────────────────
__global__ void hist_kernel(const int* __restrict__ src, int n_edges) {
    int e = blockIdx.x * blockDim.x + threadIdx.x;
    if (e < n_edges) atomicAdd(&g_counts[src[e]], 1);
}

// ── Pass 3: exclusive scan over counts (single block) ───────────────────
__global__ void scan_kernel(int n_nodes) {
    __shared__ int part[1024];
    const int tid = threadIdx.x;
    const int per = (n_nodes + 1023) >> 10;
    const int base = tid * per;

    int sum = 0;
    for (int i = 0; i < per; i++) {
        int idx = base + i;
        if (idx < n_nodes) sum += g_counts[idx];
    }
    part[tid] = sum;
    __syncthreads();

    #pragma unroll
    for (int off = 1; off < 1024; off <<= 1) {
        int v = (tid >= off) ? part[tid - off] : 0;
        __syncthreads();
        part[tid] += v;
        __syncthreads();
    }

    int run = (tid == 0) ? 0 : part[tid - 1];
    for (int i = 0; i < per; i++) {
        int idx = base + i;
        if (idx < n_nodes) {
            g_off[idx] = run;
            g_cursor[idx] = run;
            run += g_counts[idx];
        }
    }
}

// ── Pass 4: scatter edges into src-buckets ──────────────────────────────
__global__ void scatter_kernel(const int* __restrict__ src,
                               const int* __restrict__ dst, int n_edges) {
    int e = blockIdx.x * blockDim.x + threadIdx.x;
    if (e < n_edges) {
        int p = atomicAdd(&g_cursor[src[e]], 1);
        g_dst_sorted[p] = dst[e];
        g_eid_sorted[p] = e;
    }
}

// ── Pass 5: bucketed dot. Warp per src node; src vector in registers. ───
__global__ __launch_bounds__(256)
void bucket_dot_kernel(const float4* __restrict__ h,
                       float* __restrict__ out, int n_nodes) {
    const int lane  = threadIdx.x & 31;
    const int octet = lane >> 3;
    const int warp  = (blockIdx.x * blockDim.x + threadIdx.x) >> 5;
    const int nw    = (gridDim.x * blockDim.x) >> 5;

    for (int u = warp; u < n_nodes; u += nw) {
        const float4 su = __ldg(&h[(long)u * 32 + lane]);  // src vec, regs
        const int beg = g_off[u];
        const int end = beg + g_counts[u];

        int i = beg;
        // 8 edges per iteration: 8 independent coalesced gathers in flight
        for (; i + 8 <= end; i += 8) {
            const int d0 = __ldg(&g_dst_sorted[i + 0]);
            const int d1 = __ldg(&g_dst_sorted[i + 1]);
            const int d2 = __ldg(&g_dst_sorted[i + 2]);
            const int d3 = __ldg(&g_dst_sorted[i + 3]);
            const int d4 = __ldg(&g_dst_sorted[i + 4]);
            const int d5 = __ldg(&g_dst_sorted[i + 5]);
            const int d6 = __ldg(&g_dst_sorted[i + 6]);
            const int d7 = __ldg(&g_dst_sorted[i + 7]);

            const float4 b0 = __ldg(&h[(long)d0 * 32 + lane]);
            const float4 b1 = __ldg(&h[(long)d1 * 32 + lane]);
            const float4 b2 = __ldg(&h[(long)d2 * 32 + lane]);
            const float4 b3 = __ldg(&h[(long)d3 * 32 + lane]);
            const float4 b4 = __ldg(&h[(long)d4 * 32 + lane]);
            const float4 b5 = __ldg(&h[(long)d5 * 32 + lane]);
            const float4 b6 = __ldg(&h[(long)d6 * 32 + lane]);
            const float4 b7 = __ldg(&h[(long)d7 * 32 + lane]);

            float r0 = red2(dot4(su, b0));
            float r1 = red2(dot4(su, b1));
            float r2 = red2(dot4(su, b2));
            float r3 = red2(dot4(su, b3));
            float r4 = red2(dot4(su, b4));
            float r5 = red2(dot4(su, b5));
            float r6 = red2(dot4(su, b6));
            float r7 = red2(dot4(su, b7));

            // Octet q finishes edges i+2q and i+2q+1
            float va = (octet & 2) ? ((octet & 1) ? r6 : r4)
                                   : ((octet & 1) ? r2 : r0);
            float vb = (octet & 2) ? ((octet & 1) ? r7 : r5)
                                   : ((octet & 1) ? r3 : r1);
            va = red3(va);
            vb = red3(vb);

            if ((lane & 7) == 0) {
                out[__ldg(&g_eid_sorted[i + 2 * octet])]     = va;
                out[__ldg(&g_eid_sorted[i + 2 * octet + 1])] = vb;
            }
        }
        // Tail edges of this bucket
        for (; i < end; i++) {
            const int d = __ldg(&g_dst_sorted[i]);
            const float4 b = __ldg(&h[(long)d * 32 + lane]);
            float r = warp_bfly_sum(dot4(su, b));
            if (lane == 0) out[__ldg(&g_eid_sorted[i])] = r;
        }
    }
}

// ── Fallback (R5 persistent kernel) for out-of-cap shapes ───────────────
__global__ __launch_bounds__(256)
void edge_dot8_pers_kernel(const float4* __restrict__ h,
                           const int4* __restrict__ src4,
                           const int4* __restrict__ dst4,
                           float2* __restrict__ out2,
                           int n_groups) {
    const int lane    = threadIdx.x & 31;
    const int octet   = lane >> 3;
    const int gwarp   = (blockIdx.x * blockDim.x + threadIdx.x) >> 5;
    const int n_warps = (gridDim.x * blockDim.x) >> 5;

    int g = gwarp;
    if (g >= n_groups) return;
    int4 s0 = __ldg(&src4[2 * g]);
    int4 s1 = __ldg(&src4[2 * g + 1]);
    int4 d0 = __ldg(&dst4[2 * g]);
    int4 d1 = __ldg(&dst4[2 * g + 1]);

    while (true) {
        const float4 a0 = __ldg(&h[(long)s0.x * 32 + lane]);
        const float4 b0 = __ldg(&h[(long)d0.x * 32 + lane]);
        const float4 a1 = __ldg(&h[(long)s0.y * 32 + lane]);
        const float4 b1 = __ldg(&h[(long)d0.y * 32 + lane]);
        const float4 a2 = __ldg(&h[(long)s0.z * 32 + lane]);
        const float4 b2 = __ldg(&h[(long)d0.z * 32 + lane]);
        const float4 a3 = __ldg(&h[(long)s0.w * 32 + lane]);
        const float4 b3 = __ldg(&h[(long)d0.w * 32 + lane]);
        const float4 a4 = __ldg(&h[(long)s1.x * 32 + lane]);
        const float4 b4 = __ldg(&h[(long)d1.x * 32 + lane]);
        const float4 a5 = __ldg(&h[(long)s1.y * 32 + lane]);
        const float4 b5 = __ldg(&h[(long)d1.y * 32 + lane]);
        const float4 a6 = __ldg(&h[(long)s1.z * 32 + lane]);
        const float4 b6 = __ldg(&h[(long)d1.z * 32 + lane]);
        const float4 a7 = __ldg(&h[(long)s1.w * 32 + lane]);
        const float4 b7 = __ldg(&h[(long)d1.w * 32 + lane]);

        const int gn = g + n_warps;
        const bool more = (gn < n_groups);
        int4 ns0, ns1, nd0, nd1;
        if (more) {
            ns0 = __ldg(&src4[2 * gn]);
            ns1 = __ldg(&src4[2 * gn + 1]);
            nd0 = __ldg(&dst4[2 * gn]);
            nd1 = __ldg(&dst4[2 * gn + 1]);
        }

        float r0 = red2(dot4(a0, b0));
        float r1 = red2(dot4(a1, b1));
        float r2 = red2(dot4(a2, b2));
        float r3 = red2(dot4(a3, b3));
        float r4 = red2(dot4(a4, b4));
        float r5 = red2(dot4(a5, b5));
        float r6 = red2(dot4(a6, b6));
        float r7 = red2(dot4(a7, b7));

        float va = (octet & 2) ? ((octet & 1) ? r6 : r4)
                               : ((octet & 1) ? r2 : r0);
        float vb = (octet & 2) ? ((octet & 1) ? r7 : r5)
                               : ((octet & 1) ? r3 : r1);
        va = red3(va);
        vb = red3(vb);

        if ((lane & 7) == 0) out2[4 * g + octet] = make_float2(va, vb);

        if (!more) break;
        s0 = ns0; s1 = ns1; d0 = nd0; d1 = nd1;
        g = gn;
    }
}

__global__ void edge_dot_tail_kernel(const float4* __restrict__ h,
                                     const int* __restrict__ src,
                                     const int* __restrict__ dst,
                                     float* __restrict__ out,
                                     int base, int n_edges) {
    const int e    = base + ((blockIdx.x * blockDim.x + threadIdx.x) >> 5);
    const int lane = threadIdx.x & 31;
    if (e >= n_edges) return;
    const int s = __ldg(&src[e]);
    const int d = __ldg(&dst[e]);
    const float4 va = __ldg(&h[(long)s * 32 + lane]);
    const float4 vb = __ldg(&h[(long)d * 32 + lane]);
    float r = warp_bfly_sum(dot4(va, vb));
    if (lane == 0) out[e] = r;
}

extern "C" void kernel_launch(void* const* d_in, const int* in_sizes, int n_in,
                              void* d_out, int out_size) {
    // Inputs: h [N,128] f32, src [E] i32, dst [E] i32 (jax x64 disabled)
    const float4* h   = (const float4*)d_in[0];
    const int*    src = (const int*)d_in[1];
    const int*    dst = (const int*)d_in[2];
    float*        out = (float*)d_out;

    const int n_edges = in_sizes[1];          // 640000
    const int n_nodes = in_sizes[0] / 128;    // 10000

    if (n_nodes <= CAP_N && n_edges <= CAP_E) {
        const int T = 256;
        zero_kernel<<<(n_nodes + T - 1) / T, T>>>(n_nodes);
        hist_kernel<<<(n_edges + T - 1) / T, T>>>(src, n_edges);
        scan_kernel<<<1, 1024>>>(n_nodes);
        scatter_kernel<<<(n_edges + T - 1) / T, T>>>(src, dst, n_edges);

        int blocks = 148 * 4;
        const int wpb = T / 32;
        const int max_blocks = (n_nodes + wpb - 1) / wpb;
        if (blocks > max_blocks) blocks = max_blocks;
        bucket_dot_kernel<<<blocks, T>>>(h, out, n_nodes);
    } else {
        // Fallback: persistent 8-edges-per-warp kernel
        const int n_groups = n_edges / 8;
        const int tail     = n_edges - n_groups * 8;
        if (n_groups > 0) {
            const int threads = 256;
            int blocks = 148 * 4;
            const int wpb = threads / 32;
            const int max_blocks = (n_groups + wpb - 1) / wpb;
            if (blocks > max_blocks) blocks = max_blocks;
            edge_dot8_pers_kernel<<<blocks, threads>>>(h, (const int4*)src,
                                                       (const int4*)dst,
                                                       (float2*)out, n_groups);
        }
        if (tail > 0) {
            edge_dot_tail_kernel<<<1, 256>>>(h, src, dst, out,
                                             n_groups * 8, n_edges);
        }
    }
}

// round 8
// speedup vs baseline: 1.4683x; 1.4683x over previous
#include <cuda_runtime.h>
#include <cstdint>

// out[e] = dot(h[src[e]], h[dst[e]]), D=128 fp32.
// Persistent warps, 8 edges per warp-iteration, software-pipelined index
// prefetch. __launch_bounds__(256,5) caps regs at 51 so 5 blocks/SM fit
// (40 warps, ~62% occ) — R5 at 58 regs was stuck at 4 blocks (48% occ).

__device__ __forceinline__ float dot4(float4 a, float4 b) {
    float s = a.x * b.x;
    s = fmaf(a.y, b.y, s);
    s = fmaf(a.z, b.z, s);
    s = fmaf(a.w, b.w, s);
    return s;
}

__device__ __forceinline__ float red2(float v) {   // xor16 + xor8
    v += __shfl_xor_sync(0xFFFFFFFFu, v, 16);
    v += __shfl_xor_sync(0xFFFFFFFFu, v, 8);
    return v;
}

__device__ __forceinline__ float red3(float v) {   // xor4 + xor2 + xor1
    v += __shfl_xor_sync(0xFFFFFFFFu, v, 4);
    v += __shfl_xor_sync(0xFFFFFFFFu, v, 2);
    v += __shfl_xor_sync(0xFFFFFFFFu, v, 1);
    return v;
}

__device__ __forceinline__ float warp_bfly_sum(float v) {
    #pragma unroll
    for (int off = 16; off > 0; off >>= 1)
        v += __shfl_xor_sync(0xFFFFFFFFu, v, off);
    return v;
}

__global__ __launch_bounds__(256, 5)
void edge_dot8_pers_kernel(const float4* __restrict__ h,
                           const int4* __restrict__ src4,
                           const int4* __restrict__ dst4,
                           float2* __restrict__ out2,
                           int n_groups) {
    const int lane    = threadIdx.x & 31;
    const int octet   = lane >> 3;
    const int gwarp   = (blockIdx.x * blockDim.x + threadIdx.x) >> 5;
    const int n_warps = (gridDim.x * blockDim.x) >> 5;

    int g = gwarp;
    if (g >= n_groups) return;

    // Prologue: load first group's indices
    int4 s0 = __ldg(&src4[2 * g]);
    int4 s1 = __ldg(&src4[2 * g + 1]);
    int4 d0 = __ldg(&dst4[2 * g]);
    int4 d1 = __ldg(&dst4[2 * g + 1]);

    while (true) {
        const float4 a0 = __ldg(&h[(long)s0.x * 32 + lane]);
        const float4 b0 = __ldg(&h[(long)d0.x * 32 + lane]);
        const float4 a1 = __ldg(&h[(long)s0.y * 32 + lane]);
        const float4 b1 = __ldg(&h[(long)d0.y * 32 + lane]);
        const float4 a2 = __ldg(&h[(long)s0.z * 32 + lane]);
        const float4 b2 = __ldg(&h[(long)d0.z * 32 + lane]);
        const float4 a3 = __ldg(&h[(long)s0.w * 32 + lane]);
        const float4 b3 = __ldg(&h[(long)d0.w * 32 + lane]);
        const float4 a4 = __ldg(&h[(long)s1.x * 32 + lane]);
        const float4 b4 = __ldg(&h[(long)d1.x * 32 + lane]);
        const float4 a5 = __ldg(&h[(long)s1.y * 32 + lane]);
        const float4 b5 = __ldg(&h[(long)d1.y * 32 + lane]);
        const float4 a6 = __ldg(&h[(long)s1.z * 32 + lane]);
        const float4 b6 = __ldg(&h[(long)d1.z * 32 + lane]);
        const float4 a7 = __ldg(&h[(long)s1.w * 32 + lane]);
        const float4 b7 = __ldg(&h[(long)d1.w * 32 + lane]);

        // Prefetch next group's indices while gathers are in flight
        const int gn = g + n_warps;
        const bool more = (gn < n_groups);
        int4 ns0, ns1, nd0, nd1;
        if (more) {
            ns0 = __ldg(&src4[2 * gn]);
            ns1 = __ldg(&src4[2 * gn + 1]);
            nd0 = __ldg(&dst4[2 * gn]);
            nd1 = __ldg(&dst4[2 * gn + 1]);
        }

        float r0 = red2(dot4(a0, b0));
        float r1 = red2(dot4(a1, b1));
        float r2 = red2(dot4(a2, b2));
        float r3 = red2(dot4(a3, b3));
        float r4 = red2(dot4(a4, b4));
        float r5 = red2(dot4(a5, b5));
        float r6 = red2(dot4(a6, b6));
        float r7 = red2(dot4(a7, b7));

        // After xor16+xor8, value at lane l depends only on (l & 7),
        // replicated across octets. Octet q finishes edges 2q, 2q+1.
        float va = (octet & 2) ? ((octet & 1) ? r6 : r4)
                               : ((octet & 1) ? r2 : r0);
        float vb = (octet & 2) ? ((octet & 1) ? r7 : r5)
                               : ((octet & 1) ? r3 : r1);
        va = red3(va);
        vb = red3(vb);

        if ((lane & 7) == 0) out2[4 * g + octet] = make_float2(va, vb);

        if (!more) break;
        s0 = ns0; s1 = ns1; d0 = nd0; d1 = nd1;
        g = gn;
    }
}

// Tail: one warp per edge (launched only when n_edges % 8 != 0)
__global__ void edge_dot_tail_kernel(const float4* __restrict__ h,
                                     const int* __restrict__ src,
                                     const int* __restrict__ dst,
                                     float* __restrict__ out,
                                     int base, int n_edges) {
    const int e    = base + ((blockIdx.x * blockDim.x + threadIdx.x) >> 5);
    const int lane = threadIdx.x & 31;
    if (e >= n_edges) return;
    const int s = __ldg(&src[e]);
    const int d = __ldg(&dst[e]);
    const float4 va = __ldg(&h[(long)s * 32 + lane]);
    const float4 vb = __ldg(&h[(long)d * 32 + lane]);
    float r = warp_bfly_sum(dot4(va, vb));
    if (lane == 0) out[e] = r;
}

extern "C" void kernel_launch(void* const* d_in, const int* in_sizes, int n_in,
                              void* d_out, int out_size) {
    // Inputs: h [N,128] f32, src [E] i32, dst [E] i32 (jax x64 disabled)
    const float4* h   = (const float4*)d_in[0];
    const int*    src = (const int*)d_in[1];
    const int*    dst = (const int*)d_in[2];
    float*        out = (float*)d_out;

    const int n_edges  = in_sizes[1];        // E = 640000
    const int n_groups = n_edges / 8;        // 80000 groups of 8 edges
    const int tail     = n_edges - n_groups * 8;

    if (n_groups > 0) {
        const int threads = 256;             // 8 warps per block
        int blocks = 148 * 5;                // 5 blocks/SM -> 40 warps/SM
        const int wpb = threads / 32;
        const int max_blocks = (n_groups + wpb - 1) / wpb;
        if (blocks > max_blocks) blocks = max_blocks;
        edge_dot8_pers_kernel<<<blocks, threads>>>(h, (const int4*)src,
                                                   (const int4*)dst,
                                                   (float2*)out, n_groups);
    }
    if (tail > 0) {
        edge_dot_tail_kernel<<<1, 256>>>(h, src, dst, out,
                                         n_groups * 8, n_edges);
    }
}